// round 5
// baseline (speedup 1.0000x reference)
#include <cuda_runtime.h>
#include <cuda_bf16.h>

#define BB 1024
#define II 256
#define HH 256
#define TT 64
#define TM1 63

// ---------------- device scratch (static: no allocation allowed) ----------------
__device__ __nv_bfloat16 g_prefsb[(size_t)BB * TT * II];   // [b][u][i] bf16, 32 MB
__device__ float g_h[2][BB * HH];
__device__ float g_c[2][BB * HH];
// A = [w_in | h] bf16 hi/lo split, double-buffered on the h half
__device__ __nv_bfloat16 g_Ahi[2][(size_t)BB * 512];
__device__ __nv_bfloat16 g_Alo[2][(size_t)BB * 512];
// A2 = [h | c] bf16 hi/lo (single buffer: score(t) reads before gates(t) overwrites)
__device__ __nv_bfloat16 g_A2hi[(size_t)BB * 512];
__device__ __nv_bfloat16 g_A2lo[(size_t)BB * 512];
// W = [W_ih | W_hh] rows n=gate*256+j, bf16 hi/lo split
__device__ __nv_bfloat16 g_Whi[(size_t)1024 * 512];
__device__ __nv_bfloat16 g_Wlo[(size_t)1024 * 512];
// W_h transposed: rows u (64), k 0..511 ([h|c] order), bf16 hi/lo split
__device__ __nv_bfloat16 g_WhThi[(size_t)64 * 512];
__device__ __nv_bfloat16 g_WhTlo[(size_t)64 * 512];
__device__ float g_bias[1024];                    // b_ih + b_hh
__device__ float g_score[BB * 64];                // per-step score_h (+ b_h + y term)

// ---------------- helpers ----------------
__device__ __forceinline__ float tanhx(float x) {
    float r; asm("tanh.approx.f32 %0, %1;" : "=f"(r) : "f"(x)); return r;
}
__device__ __forceinline__ float sigm(float x) {
    return 1.0f / (1.0f + __expf(-x));
}
__device__ __forceinline__ void ldm4(unsigned* r, unsigned addr) {
    asm volatile("ldmatrix.sync.aligned.m8n8.x4.shared.b16 {%0,%1,%2,%3}, [%4];"
                 : "=r"(r[0]), "=r"(r[1]), "=r"(r[2]), "=r"(r[3]) : "r"(addr));
}
__device__ __forceinline__ void mma16816(float* d, const unsigned* a, unsigned b0, unsigned b1) {
    asm volatile(
        "mma.sync.aligned.m16n8k16.row.col.f32.bf16.bf16.f32 "
        "{%0,%1,%2,%3}, {%4,%5,%6,%7}, {%8,%9}, {%0,%1,%2,%3};"
        : "+f"(d[0]), "+f"(d[1]), "+f"(d[2]), "+f"(d[3])
        : "r"(a[0]), "r"(a[1]), "r"(a[2]), "r"(a[3]), "r"(b0), "r"(b1));
}
__device__ __forceinline__ void cp16(unsigned saddr, const void* g) {
    asm volatile("cp.async.cg.shared.global [%0], [%1], 16;" :: "r"(saddr), "l"(g));
}
__device__ __forceinline__ void stcs2(float* p, float2 v) {
    asm volatile("st.global.cs.v2.f32 [%0], {%1,%2};" :: "l"(p), "f"(v.x), "f"(v.y));
}
__device__ __forceinline__ void stcs1(float* p, float v) {
    asm volatile("st.global.cs.f32 [%0], %1;" :: "l"(p), "f"(v));
}

// ---------------- init: zero h,c, A slot-0 h-region, A2 ----------------
__global__ void init_kernel() {
    int idx = blockIdx.x * 256 + threadIdx.x;       // 0 .. 512K-1
    g_A2hi[idx] = __float2bfloat16(0.f);
    g_A2lo[idx] = __float2bfloat16(0.f);
    if (idx < BB * HH) {
        g_h[0][idx] = 0.f;
        g_c[0][idx] = 0.f;
        int b = idx >> 8, j = idx & 255;
        g_Ahi[0][(size_t)b * 512 + 256 + j] = __float2bfloat16(0.f);
        g_Alo[0][(size_t)b * 512 + 256 + j] = __float2bfloat16(0.f);
    }
}

// ---------------- prep: split W / W_hT into bf16 hi/lo, combine biases ----------------
__global__ void prep_kernel(const float* __restrict__ W_ih, const float* __restrict__ W_hh,
                            const float* __restrict__ b_ih, const float* __restrict__ b_hh,
                            const float* __restrict__ W_h) {
    int idx = blockIdx.x * 256 + threadIdx.x;       // 0 .. 512K-1
    int n = idx >> 9, k = idx & 511;
    float v = (k < 256) ? W_ih[n * 256 + k] : W_hh[n * 256 + (k - 256)];
    __nv_bfloat16 hi = __float2bfloat16(v);
    g_Whi[idx] = hi;
    g_Wlo[idx] = __float2bfloat16(v - __bfloat162float(hi));
    if (idx < 64 * 512) {
        int u = idx >> 9, kk = idx & 511;
        float wv = W_h[kk * 64 + u];                // W_h is (2H, T): row k, col u
        __nv_bfloat16 h2 = __float2bfloat16(wv);
        g_WhThi[idx] = h2;
        g_WhTlo[idx] = __float2bfloat16(wv - __bfloat162float(h2));
    }
    if (idx < 1024) g_bias[idx] = b_ih[idx] + b_hh[idx];
}

// ---------------- pre_fs (bf16 out) ----------------
__global__ void prefs_kernel(const float* __restrict__ FS,
                             const float* __restrict__ W_fs,
                             const float* __restrict__ b_fs) {
    __shared__ float sFS[21 * 256];
    __shared__ float sW[21 * 64];
    __shared__ float sbf[64];
    int b = blockIdx.x, tid = threadIdx.x;
    if (tid < 64) sbf[tid] = b_fs[tid];
    __syncthreads();
    float acc[64];
#pragma unroll
    for (int u = 0; u < 64; u++) acc[u] = sbf[u];

    for (int cch = 0; cch < 3; cch++) {
        int t0 = cch * 21;
        __syncthreads();
        for (int x = tid; x < 21 * 256; x += 256) sFS[x] = FS[(size_t)b * TM1 * II + t0 * II + x];
        for (int x = tid; x < 21 * 64; x += 256) sW[x] = W_fs[t0 * 64 + x];
        __syncthreads();
        for (int t = 0; t < 21; t++) {
            float xv = sFS[t * 256 + tid];
            const float4* w4 = (const float4*)(sW + t * 64);
#pragma unroll
            for (int j = 0; j < 16; j++) {
                float4 w = w4[j];
                acc[4 * j + 0] += xv * w.x;
                acc[4 * j + 1] += xv * w.y;
                acc[4 * j + 2] += xv * w.z;
                acc[4 * j + 3] += xv * w.w;
            }
        }
    }
#pragma unroll
    for (int u = 0; u < 64; u++)
        g_prefsb[((size_t)b * 64 + u) * 256 + tid] = __float2bfloat16(acc[u]);
}

// ---------------- score: g_score[b][u] = [h|c]@W_h + b_h + y_t*wfs_last ----------------
// bf16-split MMA, grid 16 (64 b-rows each), 256 thr = 8 warps (4 m-tiles x 2 n-halves)
#define SAP 40
__global__ __launch_bounds__(256) void score_kernel(const float* __restrict__ b_h,
                                                    const float* __restrict__ W_fs,
                                                    const float* __restrict__ yh, int t) {
    __shared__ __nv_bfloat16 sAhi[64 * SAP];
    __shared__ __nv_bfloat16 sAlo[64 * SAP];
    __shared__ __nv_bfloat16 sBhi[64 * SAP];
    __shared__ __nv_bfloat16 sBlo[64 * SAP];

    int b0 = blockIdx.x * 64;
    int tid = threadIdx.x;
    int w = tid >> 5, l = tid & 31;
    int lp = l & 7, quad = l >> 3;
    int mt = w & 3, nh = w >> 2;

    unsigned aoff = (unsigned)(((mt * 16 + lp + (quad & 1) * 8) * SAP + (quad >> 1) * 8) * 2);
    unsigned uAhi = (unsigned)__cvta_generic_to_shared(sAhi) + aoff;
    unsigned uAlo = (unsigned)__cvta_generic_to_shared(sAlo) + aoff;
    unsigned uBhi[2], uBlo[2];
#pragma unroll
    for (int q2 = 0; q2 < 2; q2++) {
        unsigned boff = (unsigned)(((nh * 32 + q2 * 16 + lp + (quad >> 1) * 8) * SAP
                                    + (quad & 1) * 8) * 2);
        uBhi[q2] = (unsigned)__cvta_generic_to_shared(sBhi) + boff;
        uBlo[q2] = (unsigned)__cvta_generic_to_shared(sBlo) + boff;
    }

    int r = tid >> 2, c4 = tid & 3;
    float acc[4][4];
#pragma unroll
    for (int nt = 0; nt < 4; nt++)
#pragma unroll
        for (int d = 0; d < 4; d++) acc[nt][d] = 0.f;

    for (int kc = 0; kc < 16; kc++) {
        int k0 = kc * 32;
        __syncthreads();
        *(uint4*)(sAhi + r * SAP + c4 * 8) =
            *(const uint4*)(g_A2hi + (size_t)(b0 + r) * 512 + k0 + c4 * 8);
        *(uint4*)(sAlo + r * SAP + c4 * 8) =
            *(const uint4*)(g_A2lo + (size_t)(b0 + r) * 512 + k0 + c4 * 8);
        *(uint4*)(sBhi + r * SAP + c4 * 8) =
            *(const uint4*)(g_WhThi + (size_t)r * 512 + k0 + c4 * 8);
        *(uint4*)(sBlo + r * SAP + c4 * 8) =
            *(const uint4*)(g_WhTlo + (size_t)r * 512 + k0 + c4 * 8);
        __syncthreads();

#pragma unroll
        for (int ks = 0; ks < 2; ks++) {
            unsigned kb = ks * 32;
            unsigned ahi[4], alo[4];
            ldm4(ahi, uAhi + kb);
            ldm4(alo, uAlo + kb);
            unsigned bh[2][4], bl[2][4];
#pragma unroll
            for (int q2 = 0; q2 < 2; q2++) {
                ldm4(bh[q2], uBhi[q2] + kb);
                ldm4(bl[q2], uBlo[q2] + kb);
            }
#pragma unroll
            for (int q2 = 0; q2 < 2; q2++) {
                mma16816(acc[2 * q2],     ahi, bh[q2][0], bh[q2][1]);
                mma16816(acc[2 * q2],     ahi, bl[q2][0], bl[q2][1]);
                mma16816(acc[2 * q2],     alo, bh[q2][0], bh[q2][1]);
                mma16816(acc[2 * q2 + 1], ahi, bh[q2][2], bh[q2][3]);
                mma16816(acc[2 * q2 + 1], ahi, bl[q2][2], bl[q2][3]);
                mma16816(acc[2 * q2 + 1], alo, bh[q2][2], bh[q2][3]);
            }
        }
    }

    // epilogue: + b_h[u] + y_t[b]*wfs_last[u]
    int colb = (l & 3) * 2, row = l >> 2;
    float y2[2];
#pragma unroll
    for (int rh = 0; rh < 2; rh++)
        y2[rh] = yh[(b0 + mt * 16 + row + rh * 8) * TM1 + t];
#pragma unroll
    for (int nt = 0; nt < 4; nt++)
#pragma unroll
        for (int ch = 0; ch < 2; ch++) {
            int u = nh * 32 + nt * 8 + colb + ch;
            float bu = b_h[u];
            float wf = W_fs[63 * 64 + u];
#pragma unroll
            for (int rh = 0; rh < 2; rh++) {
                int b = b0 + mt * 16 + row + rh * 8;
                g_score[b * 64 + u] = acc[nt][rh * 2 + ch] + bu + y2[rh] * wf;
            }
        }
}

// ---------------- attention step (lite): 1 batch/block, 128 threads ----------------
__global__ __launch_bounds__(128) void attn_kernel(
        const float* __restrict__ FS, const float* __restrict__ W_attn,
        float* __restrict__ out1, int t, int cur) {
    __shared__ float s_sm[64];
    __shared__ float swa[64];
    __shared__ float red[4];

    int b = blockIdx.x;
    int tid = threadIdx.x;
    if (tid < 64) {
        s_sm[tid] = g_score[b * 64 + tid];
        swa[tid] = W_attn[tid];
    }
    __syncthreads();

    // logits over i-pair (ip = tid): all 64 u
    const __nv_bfloat162* pf = (const __nv_bfloat162*)(g_prefsb + ((size_t)b * 64) * 256) + tid;
    float ax = 0.f, ay = 0.f;
#pragma unroll 16
    for (int u = 0; u < 64; u++) {
        float2 p = __bfloat1622float2(pf[u << 7]);
        float s = s_sm[u];
        float wv = swa[u];
        ax += tanhx(s + p.x) * wv;
        ay += tanhx(s + p.y) * wv;
    }

    // softmax over 256 i (no max subtraction: |logit| <= ||W_attn||_1 ~ 2.6)
    float ex = __expf(ax), ey = __expf(ay);
    float s2 = ex + ey;
#pragma unroll
    for (int off = 16; off; off >>= 1) s2 += __shfl_xor_sync(0xffffffffu, s2, off);
    if ((tid & 31) == 0) red[tid >> 5] = s2;
    __syncthreads();
    float inv = 1.0f / ((red[0] + red[1]) + (red[2] + red[3]));

    float2 fs = *(const float2*)(FS + (size_t)b * TM1 * II + t * II + 2 * tid);
    float2 wv2 = make_float2(ex * inv * fs.x, ey * inv * fs.y);
    stcs2(out1 + (size_t)b * TM1 * II + t * II + 2 * tid, wv2);

    __nv_bfloat162 hi2, lo2;
    hi2.x = __float2bfloat16(wv2.x);
    hi2.y = __float2bfloat16(wv2.y);
    lo2.x = __float2bfloat16(wv2.x - __bfloat162float(hi2.x));
    lo2.y = __float2bfloat16(wv2.y - __bfloat162float(hi2.y));
    *(__nv_bfloat162*)(g_Ahi[cur] + (size_t)b * 512 + 2 * tid) = hi2;
    *(__nv_bfloat162*)(g_Alo[cur] + (size_t)b * 512 + 2 * tid) = lo2;
}

// ---------------- gates GEMM (bf16-split tensor core, cp.async 2-stage) + LSTM ----------------
#define ABYTES (128 * SAP * 2)            // 10240
#define BBYTES (64 * SAP * 2)             // 5120
#define STAGEB (2 * ABYTES + 2 * BBYTES)  // 30720
__global__ __launch_bounds__(256) void gates_mma_kernel(float* __restrict__ out2, int t, int cur) {
    extern __shared__ char dynsm[];
    unsigned sbase = (unsigned)__cvta_generic_to_shared(dynsm);

    int j0 = blockIdx.x * 16;
    int b0 = blockIdx.y * 128;
    int tid = threadIdx.x;
    int w = tid >> 5, l = tid & 31;
    int lp = l & 7, quad = l >> 3;
    int wrow = w * 16;

    const __nv_bfloat16* Ahi = g_Ahi[cur];
    const __nv_bfloat16* Alo = g_Alo[cur];

    unsigned aoff = (unsigned)(((wrow + lp + (quad & 1) * 8) * SAP + (quad >> 1) * 8) * 2);
    unsigned boff4[4];
#pragma unroll
    for (int q4 = 0; q4 < 4; q4++)
        boff4[q4] = (unsigned)(((q4 * 16 + lp + (quad >> 1) * 8) * SAP + (quad & 1) * 8) * 2);

    int ar0 = tid >> 2, ac4 = tid & 3;
    int br = tid >> 2, bc4 = tid & 3;
    int bng = (br >> 4) * 256 + j0 + (br & 15);

    int colb = (l & 3) * 2;
    float bias[2][2][4];
#pragma unroll
    for (int jb = 0; jb < 2; jb++)
#pragma unroll
        for (int ch = 0; ch < 2; ch++) {
            int j = j0 + jb * 8 + colb + ch;
#pragma unroll
            for (int g = 0; g < 4; g++) bias[jb][ch][g] = g_bias[g * 256 + j];
        }

    float acc[8][4];
#pragma unroll
    for (int nt = 0; nt < 8; nt++)
#pragma unroll
        for (int d = 0; d < 4; d++) acc[nt][d] = 0.f;

    auto issue = [&](int kc, int st) {
        int k0 = kc * 32;
        unsigned so = sbase + st * STAGEB;
#pragma unroll
        for (int it = 0; it < 2; it++) {
            int r = ar0 + it * 64;
            size_t goff = (size_t)(b0 + r) * 512 + k0 + ac4 * 8;
            unsigned sm = so + (unsigned)((r * SAP + ac4 * 8) * 2);
            cp16(sm, Ahi + goff);
            cp16(sm + ABYTES, Alo + goff);
        }
        size_t woff = (size_t)bng * 512 + k0 + bc4 * 8;
        unsigned smb = so + 2 * ABYTES + (unsigned)((br * SAP + bc4 * 8) * 2);
        cp16(smb, g_Whi + woff);
        cp16(smb + BBYTES, g_Wlo + woff);
        asm volatile("cp.async.commit_group;");
    };

    issue(0, 0);
    for (int kc = 0; kc < 16; kc++) {
        int st = kc & 1;
        if (kc + 1 < 16) {
            issue(kc + 1, st ^ 1);
            asm volatile("cp.async.wait_group 1;");
        } else {
            asm volatile("cp.async.wait_group 0;");
        }
        __syncthreads();

        unsigned so = sbase + st * STAGEB;
        unsigned uAhi = so + aoff, uAlo = so + ABYTES + aoff;
#pragma unroll
        for (int ks = 0; ks < 2; ks++) {
            unsigned kb = ks * 32;
            unsigned ahi[4], alo[4];
            ldm4(ahi, uAhi + kb);
            ldm4(alo, uAlo + kb);
            unsigned bh[4][4], bl[4][4];
#pragma unroll
            for (int q4 = 0; q4 < 4; q4++) {
                ldm4(bh[q4], so + 2 * ABYTES + boff4[q4] + kb);
                ldm4(bl[q4], so + 2 * ABYTES + BBYTES + boff4[q4] + kb);
            }
#pragma unroll
            for (int q4 = 0; q4 < 4; q4++) {
                mma16816(acc[2 * q4],     ahi, bh[q4][0], bh[q4][1]);
                mma16816(acc[2 * q4],     ahi, bl[q4][0], bl[q4][1]);
                mma16816(acc[2 * q4],     alo, bh[q4][0], bh[q4][1]);
                mma16816(acc[2 * q4 + 1], ahi, bh[q4][2], bh[q4][3]);
                mma16816(acc[2 * q4 + 1], ahi, bl[q4][2], bl[q4][3]);
                mma16816(acc[2 * q4 + 1], alo, bh[q4][2], bh[q4][3]);
            }
        }
        __syncthreads();
    }

    // epilogue: LSTM in registers; emit h into A (next slot) and [h|c] into A2
    const float* ccur = g_c[cur];
    float* hnxt = g_h[cur ^ 1];
    float* cnxt = g_c[cur ^ 1];
    __nv_bfloat16* Ahn = g_Ahi[cur ^ 1];
    __nv_bfloat16* Aln = g_Alo[cur ^ 1];
    int row = l >> 2;
#pragma unroll
    for (int jb = 0; jb < 2; jb++)
#pragma unroll
        for (int ch = 0; ch < 2; ch++) {
            int j = j0 + jb * 8 + colb + ch;
#pragma unroll
            for (int rh = 0; rh < 2; rh++) {
                int d = rh * 2 + ch;
                int b = b0 + wrow + row + rh * 8;
                float iv = acc[0 + jb][d] + bias[jb][ch][0];
                float fv = acc[2 + jb][d] + bias[jb][ch][1];
                float gv = acc[4 + jb][d] + bias[jb][ch][2];
                float ov = acc[6 + jb][d] + bias[jb][ch][3];
                int bidx = b * 256 + j;
                float cold = ccur[bidx];
                float cnew = sigm(fv) * cold + sigm(iv) * tanhf(gv);
                float hnew = sigm(ov) * tanhf(cnew);
                cnxt[bidx] = cnew;
                hnxt[bidx] = hnew;
                __nv_bfloat16 hh = __float2bfloat16(hnew);
                __nv_bfloat16 hl = __float2bfloat16(hnew - __bfloat162float(hh));
                Ahn[(size_t)b * 512 + 256 + j] = hh;
                Aln[(size_t)b * 512 + 256 + j] = hl;
                g_A2hi[(size_t)b * 512 + j] = hh;
                g_A2lo[(size_t)b * 512 + j] = hl;
                __nv_bfloat16 cc = __float2bfloat16(cnew);
                g_A2hi[(size_t)b * 512 + 256 + j] = cc;
                g_A2lo[(size_t)b * 512 + 256 + j] =
                    __float2bfloat16(cnew - __bfloat162float(cc));
                stcs1(out2 + (size_t)b * TM1 * 256 + t * 256 + j, hnew);
            }
        }
}

// ---------------- launch ----------------
extern "C" void kernel_launch(void* const* d_in, const int* in_sizes, int n_in,
                              void* d_out, int out_size) {
    const float* FS     = (const float*)d_in[0];
    const float* yh     = (const float*)d_in[1];
    const float* W_h    = (const float*)d_in[2];
    const float* b_h    = (const float*)d_in[3];
    const float* W_fs   = (const float*)d_in[4];
    const float* b_fs   = (const float*)d_in[5];
    const float* W_attn = (const float*)d_in[6];
    // d_in[7] = b_attn: cancels inside softmax, unused
    const float* W_ih   = (const float*)d_in[8];
    const float* W_hh   = (const float*)d_in[9];
    const float* b_ih   = (const float*)d_in[10];
    const float* b_hh   = (const float*)d_in[11];

    float* out1 = (float*)d_out;                       // input_weighted (B, 63, I)
    float* out2 = out1 + (size_t)BB * TM1 * II;        // input_encoded (B, 63, H)

    static int attr_done = 0;
    if (!attr_done) {
        cudaFuncSetAttribute(gates_mma_kernel,
                             cudaFuncAttributeMaxDynamicSharedMemorySize, 2 * STAGEB);
        attr_done = 1;
    }

    init_kernel<<<BB * 512 / 256, 256>>>();
    prep_kernel<<<1024 * 512 / 256, 256>>>(W_ih, W_hh, b_ih, b_hh, W_h);
    prefs_kernel<<<BB, 256>>>(FS, W_fs, b_fs);
    for (int t = 0; t < TM1; t++) {
        int cur = t & 1;
        score_kernel<<<16, 256>>>(b_h, W_fs, yh, t);
        attn_kernel<<<BB, 128>>>(FS, W_attn, out1, t, cur);
        gates_mma_kernel<<<dim3(16, 8), 256, 2 * STAGEB>>>(out2, t, cur);
    }
}

// round 6
// speedup vs baseline: 1.3584x; 1.3584x over previous
#include <cuda_runtime.h>
#include <cuda_bf16.h>

#define BB 1024
#define II 256
#define HH 256
#define TT 64
#define TM1 63

// ---------------- device scratch (static: no allocation allowed) ----------------
__device__ __nv_bfloat16 g_prefsb[(size_t)BB * TT * II];   // [b][u][i] bf16, 32 MB (L2-resident)
__device__ float g_h[2][BB * HH];
__device__ float g_c[2][BB * HH];
// A = [w_in | h] as bf16 hi/lo split, double-buffered on the h half: [slot][b][k0..511]
__device__ __nv_bfloat16 g_Ahi[2][(size_t)BB * 512];
__device__ __nv_bfloat16 g_Alo[2][(size_t)BB * 512];
// W = [W_ih | W_hh] rows n=gate*256+j, k 0..511, bf16 hi/lo split (computed once per launch)
__device__ __nv_bfloat16 g_Whi[(size_t)1024 * 512];
__device__ __nv_bfloat16 g_Wlo[(size_t)1024 * 512];
__device__ float g_bias[1024];                    // b_ih + b_hh

// ---------------- helpers ----------------
__device__ __forceinline__ float tanhx(float x) {
    float r; asm("tanh.approx.f32 %0, %1;" : "=f"(r) : "f"(x)); return r;
}
__device__ __forceinline__ float sigm(float x) {
    return 1.0f / (1.0f + __expf(-x));
}
__device__ __forceinline__ void ldm4(unsigned* r, unsigned addr) {
    asm volatile("ldmatrix.sync.aligned.m8n8.x4.shared.b16 {%0,%1,%2,%3}, [%4];"
                 : "=r"(r[0]), "=r"(r[1]), "=r"(r[2]), "=r"(r[3]) : "r"(addr));
}
__device__ __forceinline__ void mma16816(float* d, const unsigned* a, unsigned b0, unsigned b1) {
    asm volatile(
        "mma.sync.aligned.m16n8k16.row.col.f32.bf16.bf16.f32 "
        "{%0,%1,%2,%3}, {%4,%5,%6,%7}, {%8,%9}, {%0,%1,%2,%3};"
        : "+f"(d[0]), "+f"(d[1]), "+f"(d[2]), "+f"(d[3])
        : "r"(a[0]), "r"(a[1]), "r"(a[2]), "r"(a[3]), "r"(b0), "r"(b1));
}
__device__ __forceinline__ void cp16(unsigned saddr, const void* g) {
    asm volatile("cp.async.cg.shared.global [%0], [%1], 16;" :: "r"(saddr), "l"(g));
}
// streaming (evict-first) stores: keep out1/out2 from evicting prefs/W in L2
__device__ __forceinline__ void stcs2(float* p, float2 v) {
    asm volatile("st.global.cs.v2.f32 [%0], {%1,%2};" :: "l"(p), "f"(v.x), "f"(v.y));
}
__device__ __forceinline__ void stcs1(float* p, float v) {
    asm volatile("st.global.cs.f32 [%0], %1;" :: "l"(p), "f"(v));
}
// streaming load (no-reuse data: FS at step t)
__device__ __forceinline__ float2 ldcs2(const float* p) {
    float2 v;
    asm volatile("ld.global.cs.v2.f32 {%0,%1}, [%2];" : "=f"(v.x), "=f"(v.y) : "l"(p));
    return v;
}

// ---------------- init: zero h,c and the h-region of A slot 0 ----------------
__global__ void init_kernel() {
    int idx = blockIdx.x * 256 + threadIdx.x;
    g_h[0][idx] = 0.f;
    g_c[0][idx] = 0.f;
    int b = idx >> 8, j = idx & 255;
    g_Ahi[0][(size_t)b * 512 + 256 + j] = __float2bfloat16(0.f);
    g_Alo[0][(size_t)b * 512 + 256 + j] = __float2bfloat16(0.f);
}

// ---------------- prep: split W into bf16 hi/lo, combine biases ----------------
__global__ void prep_kernel(const float* __restrict__ W_ih, const float* __restrict__ W_hh,
                            const float* __restrict__ b_ih, const float* __restrict__ b_hh) {
    int idx = blockIdx.x * 256 + threadIdx.x;
    int n = idx >> 9, k = idx & 511;
    float v = (k < 256) ? W_ih[n * 256 + k] : W_hh[n * 256 + (k - 256)];
    __nv_bfloat16 hi = __float2bfloat16(v);
    g_Whi[idx] = hi;
    g_Wlo[idx] = __float2bfloat16(v - __bfloat162float(hi));
    if (idx < 1024) g_bias[idx] = b_ih[idx] + b_hh[idx];
}

// ---------------- pre_fs (bf16 out): [b][u][i] = sum_t FS[b][t][i]*W_fs[t][u] + b_fs[u] ----------------
__global__ void prefs_kernel(const float* __restrict__ FS,
                             const float* __restrict__ W_fs,
                             const float* __restrict__ b_fs) {
    __shared__ float sFS[21 * 256];
    __shared__ float sW[21 * 64];
    __shared__ float sbf[64];
    int b = blockIdx.x, tid = threadIdx.x;
    if (tid < 64) sbf[tid] = b_fs[tid];
    __syncthreads();
    float acc[64];
#pragma unroll
    for (int u = 0; u < 64; u++) acc[u] = sbf[u];

    for (int cch = 0; cch < 3; cch++) {
        int t0 = cch * 21;
        __syncthreads();
        for (int x = tid; x < 21 * 256; x += 256) sFS[x] = FS[(size_t)b * TM1 * II + t0 * II + x];
        for (int x = tid; x < 21 * 64; x += 256) sW[x] = W_fs[t0 * 64 + x];
        __syncthreads();
        for (int t = 0; t < 21; t++) {
            float xv = sFS[t * 256 + tid];
            const float4* w4 = (const float4*)(sW + t * 64);
#pragma unroll
            for (int j = 0; j < 16; j++) {
                float4 w = w4[j];
                acc[4 * j + 0] += xv * w.x;
                acc[4 * j + 1] += xv * w.y;
                acc[4 * j + 2] += xv * w.z;
                acc[4 * j + 3] += xv * w.w;
            }
        }
    }
#pragma unroll
    for (int u = 0; u < 64; u++)
        g_prefsb[((size_t)b * 64 + u) * 256 + tid] = __float2bfloat16(acc[u]);
}

// ---------------- attention step: 4 batches/block, 512 threads ----------------
__global__ __launch_bounds__(512) void attn_kernel(
        const float* __restrict__ FS, const float* __restrict__ yh,
        const float* __restrict__ W_h, const float* __restrict__ b_h,
        const float* __restrict__ W_fs, const float* __restrict__ W_attn,
        float* __restrict__ out1, int t, int cur) {
    __shared__ float hc[4][512];
    __shared__ float sp[8][4][64];
    __shared__ float s_sm[4][64];
    __shared__ float wa[64];
    __shared__ float2 part[4][4][128];   // [u-quarter][batch][i-pair]
    __shared__ float wrm[4][4];
    __shared__ float wrs[4][4];

    int b0 = blockIdx.x * 4;
    int tid = threadIdx.x;
    const float* hcur = g_h[cur];
    const float* ccur = g_c[cur];

    for (int x = tid; x < 4 * 512; x += 512) {
        int bb = x >> 9, k = x & 511;
        hc[bb][k] = (k < 256) ? hcur[(b0 + bb) * 256 + k] : ccur[(b0 + bb) * 256 + (k - 256)];
    }
    if (tid < 64) wa[tid] = W_attn[tid];
    __syncthreads();

    // phase 1: score_h = [h,c] @ W_h   (u = tid%64, q = tid/64 -> 8 k-chunks of 64)
    {
        int u = tid & 63, q = tid >> 6;
        float p0 = 0, p1 = 0, p2 = 0, p3 = 0;
        int kend = q * 64 + 64;
#pragma unroll 4
        for (int k = q * 64; k < kend; k++) {
            float wv = W_h[k * 64 + u];
            p0 += hc[0][k] * wv; p1 += hc[1][k] * wv;
            p2 += hc[2][k] * wv; p3 += hc[3][k] * wv;
        }
        sp[q][0][u] = p0; sp[q][1][u] = p1; sp[q][2][u] = p2; sp[q][3][u] = p3;
    }
    __syncthreads();
    if (tid < 256) {
        int bb = tid >> 6, uu = tid & 63;
        float y = yh[(b0 + bb) * TM1 + t];
        float s = b_h[uu] + y * W_fs[63 * 64 + uu];
#pragma unroll
        for (int q = 0; q < 8; q++) s += sp[q][bb][uu];
        s_sm[bb][uu] = s;
    }
    __syncthreads();

    // phase 2: partial logits over 16-u quarter, i as bf16x2 pair
    int u4 = tid >> 7, ip = tid & 127;
#pragma unroll
    for (int bb = 0; bb < 4; bb++) {
        const __nv_bfloat162* pf = (const __nv_bfloat162*)
            (g_prefsb + (((size_t)(b0 + bb) * 64 + u4 * 16) << 8)) + ip;
        float ax = 0.f, ay = 0.f;
#pragma unroll
        for (int uu = 0; uu < 16; uu++) {
            float2 p = __bfloat1622float2(pf[uu << 7]);
            float s = s_sm[bb][u4 * 16 + uu];
            float wv = wa[u4 * 16 + uu];
            ax += tanhx(s + p.x) * wv;
            ay += tanhx(s + p.y) * wv;
        }
        part[u4][bb][ip] = make_float2(ax, ay);
    }
    __syncthreads();

    // phase 3: combine quarters, softmax over i, w_in
    {
        int bb = tid >> 7;                  // batch handled by 4 warps (128 threads)
        int ipp = tid & 127;
        int lane = tid & 31, wg = (tid >> 5) & 3;
        float2 lg;
        lg.x = part[0][bb][ipp].x + part[1][bb][ipp].x + part[2][bb][ipp].x + part[3][bb][ipp].x;
        lg.y = part[0][bb][ipp].y + part[1][bb][ipp].y + part[2][bb][ipp].y + part[3][bb][ipp].y;
        float m = fmaxf(lg.x, lg.y);
#pragma unroll
        for (int off = 16; off; off >>= 1) m = fmaxf(m, __shfl_xor_sync(0xffffffffu, m, off));
        if (lane == 0) wrm[bb][wg] = m;
        __syncthreads();
        m = fmaxf(fmaxf(wrm[bb][0], wrm[bb][1]), fmaxf(wrm[bb][2], wrm[bb][3]));
        float ex = __expf(lg.x - m), ey = __expf(lg.y - m);
        float s2 = ex + ey;
#pragma unroll
        for (int off = 16; off; off >>= 1) s2 += __shfl_xor_sync(0xffffffffu, s2, off);
        if (lane == 0) wrs[bb][wg] = s2;
        __syncthreads();
        float inv = 1.0f / ((wrs[bb][0] + wrs[bb][1]) + (wrs[bb][2] + wrs[bb][3]));
        int gb = b0 + bb;
        float2 fs = ldcs2(FS + (size_t)gb * TM1 * II + t * II + 2 * ipp);
        float2 w = make_float2(ex * inv * fs.x, ey * inv * fs.y);
        stcs2(out1 + (size_t)gb * TM1 * II + t * II + 2 * ipp, w);
        __nv_bfloat162 hi2, lo2;
        hi2.x = __float2bfloat16(w.x);
        hi2.y = __float2bfloat16(w.y);
        lo2.x = __float2bfloat16(w.x - __bfloat162float(hi2.x));
        lo2.y = __float2bfloat16(w.y - __bfloat162float(hi2.y));
        *(__nv_bfloat162*)(g_Ahi[cur] + (size_t)gb * 512 + 2 * ipp) = hi2;
        *(__nv_bfloat162*)(g_Alo[cur] + (size_t)gb * 512 + 2 * ipp) = lo2;
    }
}

// ---------------- gates GEMM (bf16-split tensor core, cp.async 2-stage) + LSTM ----------------
#define SAP 40   // smem k-stride (bf16 elems)
#define ABYTES (128 * SAP * 2)            // 10240
#define BBYTES (64 * SAP * 2)             // 5120
#define STAGEB (2 * ABYTES + 2 * BBYTES)  // 30720
__global__ __launch_bounds__(256) void gates_mma_kernel(float* __restrict__ out2, int t, int cur) {
    extern __shared__ char dynsm[];
    unsigned sbase = (unsigned)__cvta_generic_to_shared(dynsm);

    int j0 = blockIdx.x * 16;
    int b0 = blockIdx.y * 128;
    int tid = threadIdx.x;
    int w = tid >> 5, l = tid & 31;
    int lp = l & 7, quad = l >> 3;
    int wrow = w * 16;

    const __nv_bfloat16* Ahi = g_Ahi[cur];
    const __nv_bfloat16* Alo = g_Alo[cur];

    unsigned aoff = (unsigned)(((wrow + lp + (quad & 1) * 8) * SAP + (quad >> 1) * 8) * 2);
    unsigned boff4[4];
#pragma unroll
    for (int q4 = 0; q4 < 4; q4++)
        boff4[q4] = (unsigned)(((q4 * 16 + lp + (quad >> 1) * 8) * SAP + (quad & 1) * 8) * 2);

    int ar0 = tid >> 2, ac4 = tid & 3;
    int br = tid >> 2, bc4 = tid & 3;
    int bng = (br >> 4) * 256 + j0 + (br & 15);

    int colb = (l & 3) * 2;
    float bias[2][2][4];
#pragma unroll
    for (int jb = 0; jb < 2; jb++)
#pragma unroll
        for (int ch = 0; ch < 2; ch++) {
            int j = j0 + jb * 8 + colb + ch;
#pragma unroll
            for (int g = 0; g < 4; g++) bias[jb][ch][g] = g_bias[g * 256 + j];
        }

    float acc[8][4];
#pragma unroll
    for (int nt = 0; nt < 8; nt++)
#pragma unroll
        for (int d = 0; d < 4; d++) acc[nt][d] = 0.f;

    auto issue = [&](int kc, int st) {
        int k0 = kc * 32;
        unsigned so = sbase + st * STAGEB;
#pragma unroll
        for (int it = 0; it < 2; it++) {
            int r = ar0 + it * 64;
            size_t goff = (size_t)(b0 + r) * 512 + k0 + ac4 * 8;
            unsigned sm = so + (unsigned)((r * SAP + ac4 * 8) * 2);
            cp16(sm, Ahi + goff);
            cp16(sm + ABYTES, Alo + goff);
        }
        size_t woff = (size_t)bng * 512 + k0 + bc4 * 8;
        unsigned smb = so + 2 * ABYTES + (unsigned)((br * SAP + bc4 * 8) * 2);
        cp16(smb, g_Whi + woff);
        cp16(smb + BBYTES, g_Wlo + woff);
        asm volatile("cp.async.commit_group;");
    };

    issue(0, 0);
    for (int kc = 0; kc < 16; kc++) {
        int st = kc & 1;
        if (kc + 1 < 16) {
            issue(kc + 1, st ^ 1);
            asm volatile("cp.async.wait_group 1;");
        } else {
            asm volatile("cp.async.wait_group 0;");
        }
        __syncthreads();

        unsigned so = sbase + st * STAGEB;
        unsigned uAhi = so + aoff, uAlo = so + ABYTES + aoff;
#pragma unroll
        for (int ks = 0; ks < 2; ks++) {
            unsigned kb = ks * 32;
            unsigned ahi[4], alo[4];
            ldm4(ahi, uAhi + kb);
            ldm4(alo, uAlo + kb);
            unsigned bh[4][4], bl[4][4];
#pragma unroll
            for (int q4 = 0; q4 < 4; q4++) {
                ldm4(bh[q4], so + 2 * ABYTES + boff4[q4] + kb);
                ldm4(bl[q4], so + 2 * ABYTES + BBYTES + boff4[q4] + kb);
            }
#pragma unroll
            for (int q4 = 0; q4 < 4; q4++) {
                mma16816(acc[2 * q4],     ahi, bh[q4][0], bh[q4][1]);
                mma16816(acc[2 * q4],     ahi, bl[q4][0], bl[q4][1]);
                mma16816(acc[2 * q4],     alo, bh[q4][0], bh[q4][1]);
                mma16816(acc[2 * q4 + 1], ahi, bh[q4][2], bh[q4][3]);
                mma16816(acc[2 * q4 + 1], ahi, bl[q4][2], bl[q4][3]);
                mma16816(acc[2 * q4 + 1], alo, bh[q4][2], bh[q4][3]);
            }
        }
        __syncthreads();
    }

    // epilogue: LSTM in registers
    const float* ccur = g_c[cur];
    float* hnxt = g_h[cur ^ 1];
    float* cnxt = g_c[cur ^ 1];
    __nv_bfloat16* Ahn = g_Ahi[cur ^ 1];
    __nv_bfloat16* Aln = g_Alo[cur ^ 1];
    int row = l >> 2;
#pragma unroll
    for (int jb = 0; jb < 2; jb++)
#pragma unroll
        for (int ch = 0; ch < 2; ch++) {
            int j = j0 + jb * 8 + colb + ch;
#pragma unroll
            for (int rh = 0; rh < 2; rh++) {
                int d = rh * 2 + ch;
                int b = b0 + wrow + row + rh * 8;
                float iv = acc[0 + jb][d] + bias[jb][ch][0];
                float fv = acc[2 + jb][d] + bias[jb][ch][1];
                float gv = acc[4 + jb][d] + bias[jb][ch][2];
                float ov = acc[6 + jb][d] + bias[jb][ch][3];
                int bidx = b * 256 + j;
                float cold = ccur[bidx];
                float cnew = sigm(fv) * cold + sigm(iv) * tanhf(gv);
                float hnew = sigm(ov) * tanhf(cnew);
                cnxt[bidx] = cnew;
                hnxt[bidx] = hnew;
                __nv_bfloat16 hh = __float2bfloat16(hnew);
                Ahn[(size_t)b * 512 + 256 + j] = hh;
                Aln[(size_t)b * 512 + 256 + j] = __float2bfloat16(hnew - __bfloat162float(hh));
                stcs1(out2 + (size_t)b * TM1 * 256 + t * 256 + j, hnew);
            }
        }
}

// ---------------- launch ----------------
extern "C" void kernel_launch(void* const* d_in, const int* in_sizes, int n_in,
                              void* d_out, int out_size) {
    const float* FS     = (const float*)d_in[0];
    const float* yh     = (const float*)d_in[1];
    const float* W_h    = (const float*)d_in[2];
    const float* b_h    = (const float*)d_in[3];
    const float* W_fs   = (const float*)d_in[4];
    const float* b_fs   = (const float*)d_in[5];
    const float* W_attn = (const float*)d_in[6];
    // d_in[7] = b_attn: cancels inside softmax, unused
    const float* W_ih   = (const float*)d_in[8];
    const float* W_hh   = (const float*)d_in[9];
    const float* b_ih   = (const float*)d_in[10];
    const float* b_hh   = (const float*)d_in[11];

    float* out1 = (float*)d_out;                       // input_weighted (B, 63, I)
    float* out2 = out1 + (size_t)BB * TM1 * II;        // input_encoded (B, 63, H)

    static int attr_done = 0;
    if (!attr_done) {
        cudaFuncSetAttribute(gates_mma_kernel,
                             cudaFuncAttributeMaxDynamicSharedMemorySize, 2 * STAGEB);
        attr_done = 1;
    }

    init_kernel<<<BB * HH / 256, 256>>>();
    prep_kernel<<<1024 * 512 / 256, 256>>>(W_ih, W_hh, b_ih, b_hh);
    prefs_kernel<<<BB, 256>>>(FS, W_fs, b_fs);
    for (int t = 0; t < TM1; t++) {
        int cur = t & 1;
        attn_kernel<<<BB / 4, 512>>>(FS, yh, W_h, b_h, W_fs, W_attn, out1, t, cur);
        gates_mma_kernel<<<dim3(16, 8), 256, 2 * STAGEB>>>(out2, t, cur);
    }
}